// round 8
// baseline (speedup 1.0000x reference)
#include <cuda_runtime.h>

#define DIM 16777216

__device__ __forceinline__ float spu(float v) {
    // v >= 0 : v*v - 0.5
    // v <  0 : sigmoid(-v) - 1 = 1/(1+e^v) - 1
    float pos = fmaf(v, v, -0.5f);
    float e = __expf(v);
    float neg = __fdividef(1.0f, 1.0f + e) - 1.0f;
    return (v >= 0.0f) ? pos : neg;
}

struct f8 { float v[8]; };

__device__ __forceinline__ f8 ldg256(const float* p) {
    f8 r;
    asm volatile("ld.global.nc.v8.f32 {%0,%1,%2,%3,%4,%5,%6,%7}, [%8];"
                 : "=f"(r.v[0]), "=f"(r.v[1]), "=f"(r.v[2]), "=f"(r.v[3]),
                   "=f"(r.v[4]), "=f"(r.v[5]), "=f"(r.v[6]), "=f"(r.v[7])
                 : "l"(p));
    return r;
}

__device__ __forceinline__ void stg256(float* p, const f8& r) {
    asm volatile("st.global.v8.f32 [%0], {%1,%2,%3,%4,%5,%6,%7,%8};"
                 :: "l"(p),
                    "f"(r.v[0]), "f"(r.v[1]), "f"(r.v[2]), "f"(r.v[3]),
                    "f"(r.v[4]), "f"(r.v[5]), "f"(r.v[6]), "f"(r.v[7])
                 : "memory");
}

__global__ void __launch_bounds__(256) spu_box_kernel_v8(
    const float* __restrict__ x,
    const float* __restrict__ l,
    const float* __restrict__ u,
    float* __restrict__ out_x,
    float* __restrict__ out_l,
    float* __restrict__ out_u)
{
    // 8 floats per thread; grid divides exactly (no tail).
    long long base = (long long)(blockIdx.x * blockDim.x + threadIdx.x) * 8;

    f8 xv = ldg256(x + base);
    f8 lv = ldg256(l + base);
    f8 uv = ldg256(u + base);

    f8 ox, ol, ou;

    #pragma unroll
    for (int k = 0; k < 8; k++) {
        float ls = lv.v[k];
        float us = uv.v[k];

        float spu_l = spu(ls);
        float spu_u = spu(us);

        float lo, uo;
        if (ls >= 0.0f) {
            lo = spu_l;
            uo = spu_u;
        } else if (us <= 0.0f) {
            lo = spu_u;
            uo = spu(spu_u);   // faithful: u' = spu(spu(u))
        } else {
            lo = -0.5f;
            uo = spu_u;
        }

        ox.v[k] = spu(xv.v[k]);
        ol.v[k] = lo;
        ou.v[k] = uo;
    }

    stg256(out_x + base, ox);
    stg256(out_l + base, ol);
    stg256(out_u + base, ou);
}

extern "C" void kernel_launch(void* const* d_in, const int* in_sizes, int n_in,
                              void* d_out, int out_size) {
    const float* x = (const float*)d_in[0];
    const float* l = (const float*)d_in[1];
    const float* u = (const float*)d_in[2];

    float* out   = (float*)d_out;
    float* out_x = out;
    float* out_l = out + DIM;
    float* out_u = out + 2 * DIM;

    int threads = 256;
    int blocks = DIM / (threads * 8);   // 8192, exact
    spu_box_kernel_v8<<<blocks, threads>>>(x, l, u, out_x, out_l, out_u);
}

// round 9
// speedup vs baseline: 1.0172x; 1.0172x over previous
#include <cuda_runtime.h>

#define DIM 16777216

__device__ __forceinline__ float spu(float v) {
    // v >= 0 : v*v - 0.5
    // v <  0 : sigmoid(-v) - 1 = 1/(1+e^v) - 1
    float pos = fmaf(v, v, -0.5f);
    float e = __expf(v);
    float neg = __fdividef(1.0f, 1.0f + e) - 1.0f;
    return (v >= 0.0f) ? pos : neg;
}

__global__ void __launch_bounds__(256) spu_box_kernel(
    const float4* __restrict__ x,
    const float4* __restrict__ l,
    const float4* __restrict__ u,
    float4* __restrict__ out_x,
    float4* __restrict__ out_l,
    float4* __restrict__ out_u,
    int n4)
{
    int i = blockIdx.x * blockDim.x + threadIdx.x;
    if (i >= n4) return;

    // Three independent, perfectly coalesced 128-bit loads (MLP=3).
    float4 xv = x[i];
    float4 lv = l[i];
    float4 uv = u[i];

    float4 ox, ol, ou;

    #pragma unroll
    for (int k = 0; k < 4; k++) {
        float xs = (&xv.x)[k];
        float ls = (&lv.x)[k];
        float us = (&uv.x)[k];

        float spu_l = spu(ls);
        float spu_u = spu(us);

        float lo, uo;
        if (ls >= 0.0f) {
            lo = spu_l;
            uo = spu_u;
        } else if (us <= 0.0f) {
            lo = spu_u;
            uo = spu(spu_u);   // faithful to reference: u' = spu(spu(u))
        } else {
            lo = -0.5f;
            uo = spu_u;
        }

        (&ox.x)[k] = spu(xs);
        (&ol.x)[k] = lo;
        (&ou.x)[k] = uo;
    }

    out_x[i] = ox;
    out_l[i] = ol;
    out_u[i] = ou;
}

extern "C" void kernel_launch(void* const* d_in, const int* in_sizes, int n_in,
                              void* d_out, int out_size) {
    const float4* x = (const float4*)d_in[0];
    const float4* l = (const float4*)d_in[1];
    const float4* u = (const float4*)d_in[2];

    float* out = (float*)d_out;
    float4* out_x = (float4*)(out);
    float4* out_l = (float4*)(out + DIM);
    float4* out_u = (float4*)(out + 2 * DIM);

    int n4 = DIM / 4;                  // 4194304
    int threads = 256;
    int blocks = (n4 + threads - 1) / threads;   // 16384
    spu_box_kernel<<<blocks, threads>>>(x, l, u, out_x, out_l, out_u, n4);
}